// round 1
// baseline (speedup 1.0000x reference)
#include <cuda_runtime.h>
#include <cuda_bf16.h>

// Problem constants
#define NB   4
#define NT   128
#define NC   8
#define NIMG 512          // NB*NT
#define HW   1024         // 32*32
#define KIDX 9
#define HID  64
#define CHUNK 8           // input-channel chunk held in smem

// ---------------- scratch (device globals; no runtime allocation) ------------
__device__ float g_resin[NIMG * 25 * HW];    // 52.4 MB  (res_in; ch 0..7 = z_base)
__device__ float g_h[NIMG * HID * HW];       // 134 MB
__device__ float g_tmp[NIMG * HID * HW];     // 134 MB
__device__ float g_cout[NIMG * 9 * HW];      // 18.9 MB
__device__ float g_alpha[NIMG];
__device__ float g_araw[NIMG];

// ---------------- prep: gather/lerp + build res_in ---------------------------
__global__ __launch_bounds__(256)
void prep_kernel(const float* __restrict__ latents, const int* __restrict__ idx,
                 float* __restrict__ resin, float* __restrict__ alpha_arr,
                 float* __restrict__ araw_arr)
{
    const int n = blockIdx.x;          // image index = b*NT + t
    const int b = n >> 7;
    const int t = n & 127;

    // load + insertion-sort the 9 keyframe indices (redundant per thread, cheap)
    int v[KIDX];
#pragma unroll
    for (int k = 0; k < KIDX; k++) v[k] = idx[b * KIDX + k];
#pragma unroll
    for (int i = 1; i < KIDX; i++) {
        int key = v[i]; int j = i - 1;
        while (j >= 0 && v[j] > key) { v[j + 1] = v[j]; j--; }
        v[j + 1] = key;
    }
    // searchsorted(right) - 1, clipped to [0, K-2]
    int cnt = 0;
#pragma unroll
    for (int k = 0; k < KIDX; k++) cnt += (v[k] <= t);
    int seg = cnt - 1;
    seg = min(max(seg, 0), KIDX - 2);
    const int t0 = v[seg], t1 = v[seg + 1];
    const float araw = (float)(t - t0) / (float)max(t1 - t0, 1);
    const float a = fminf(fmaxf(araw, 0.f), 1.f);

    const int tid = threadIdx.x;
    const float* L0 = latents + (size_t)(b * NT + t0) * NC * HW;
    const float* L1 = latents + (size_t)(b * NT + t1) * NC * HW;
    float* R = resin + (size_t)n * 25 * HW;

#pragma unroll
    for (int j = 0; j < 4; j++) {
        const int p = tid + 256 * j;
#pragma unroll
        for (int c = 0; c < NC; c++) {
            const float z0 = L0[c * HW + p];
            const float z1 = L1[c * HW + p];
            R[c * HW + p]        = (1.f - a) * z0 + a * z1;  // z_base
            R[(8 + c) * HW + p]  = z0;
            R[(16 + c) * HW + p] = z1;
        }
        R[24 * HW + p] = a;   // t_chan
    }
    if (tid == 0) { alpha_arr[n] = a; araw_arr[n] = araw; }
}

// ---------------- generic 3x3 SAME conv, tiled in smem -----------------------
// block = (image n, out-channel tile). 256 threads; each thread owns 4 pixels
// and COUT_TILE output channels. Input channels streamed in CHUNK-sized smem
// tiles with zero halo. Weights broadcast from smem (uniform address per warp).
template<int CIN, int COUT, int COUT_TILE, bool SILU, bool RESID>
__global__ __launch_bounds__(256)
void conv3x3_kernel(const float* __restrict__ in, const float* __restrict__ w,
                    const float* __restrict__ bias, float* __restrict__ out,
                    const float* __restrict__ resid)
{
    __shared__ float in_s[CHUNK][34 * 34];
    __shared__ float w_s[COUT_TILE][CHUNK][9];

    const int n   = blockIdx.x;
    const int co0 = blockIdx.y * COUT_TILE;
    const int tid = threadIdx.x;

    float acc[4][COUT_TILE];
#pragma unroll
    for (int j = 0; j < 4; j++)
#pragma unroll
        for (int co = 0; co < COUT_TILE; co++) acc[j][co] = 0.f;

    constexpr int NCHUNK = (CIN + CHUNK - 1) / CHUNK;

    for (int ch = 0; ch < NCHUNK; ch++) {
        const int c0 = ch * CHUNK;
        // load input chunk with zero halo / zero-padded trailing channels
        for (int i = tid; i < CHUNK * 1156; i += 256) {
            const int c   = i / 1156;
            const int pos = i - c * 1156;
            const int yy  = pos / 34 - 1;
            const int xx  = pos - (pos / 34) * 34 - 1;
            float val = 0.f;
            const int cg = c0 + c;
            if (cg < CIN && yy >= 0 && yy < 32 && xx >= 0 && xx < 32)
                val = in[(size_t)(n * CIN + cg) * HW + yy * 32 + xx];
            in_s[c][pos] = val;
        }
        // load weight chunk
        for (int i = tid; i < COUT_TILE * CHUNK * 9; i += 256) {
            const int tap = i % 9;
            const int c   = (i / 9) % CHUNK;
            const int co  = i / (9 * CHUNK);
            const int cg  = c0 + c;
            w_s[co][c][tap] = (cg < CIN) ? w[((co0 + co) * CIN + cg) * 9 + tap] : 0.f;
        }
        __syncthreads();

#pragma unroll 1
        for (int ci = 0; ci < CHUNK; ci++) {
#pragma unroll
            for (int tap = 0; tap < 9; tap++) {
                const int dy = tap / 3, dx = tap % 3;
                float wr[COUT_TILE];
#pragma unroll
                for (int co = 0; co < COUT_TILE; co++) wr[co] = w_s[co][ci][tap];
#pragma unroll
                for (int j = 0; j < 4; j++) {
                    const int p = tid + 256 * j;
                    const int y = p >> 5, x = p & 31;
                    const float v = in_s[ci][(y + dy) * 34 + (x + dx)];
#pragma unroll
                    for (int co = 0; co < COUT_TILE; co++)
                        acc[j][co] = fmaf(v, wr[co], acc[j][co]);
                }
            }
        }
        __syncthreads();
    }

    // epilogue: bias (+SiLU) (+residual), store
#pragma unroll
    for (int co = 0; co < COUT_TILE; co++) {
        const float bv = bias[co0 + co];
#pragma unroll
        for (int j = 0; j < 4; j++) {
            const int p = tid + 256 * j;
            float val = acc[j][co] + bv;
            if (SILU) val = val / (1.f + __expf(-val));
            const size_t o = (size_t)(n * COUT + co0 + co) * HW + p;
            if (RESID) val += resid[o];
            out[o] = val;
        }
    }
}

// ---------------- finalize: z_hat + conf -------------------------------------
__global__ __launch_bounds__(256)
void finalize_kernel(const float* __restrict__ resin, const float* __restrict__ co,
                     const float* __restrict__ alpha_arr, const float* __restrict__ araw_arr,
                     float* __restrict__ out)
{
    const int n = blockIdx.x;
    const int tid = threadIdx.x;
    const float a  = alpha_arr[n];
    const float ar = araw_arr[n];
    const float s  = a * (1.f - a);
    const bool interior = (ar > 0.f) && (ar < 1.f);

    const float* R = resin + (size_t)n * 25 * HW;
    const float* O = co + (size_t)n * 9 * HW;
    float* zhat = out + (size_t)n * NC * HW;
    float* conf = out + (size_t)NIMG * NC * HW + (size_t)n * HW;

#pragma unroll
    for (int j = 0; j < 4; j++) {
        const int p = tid + 256 * j;
#pragma unroll
        for (int c = 0; c < NC; c++)
            zhat[c * HW + p] = R[c * HW + p] + s * O[c * HW + p];
        const float logit = O[8 * HW + p];
        const float unc = 1.f / (1.f + __expf(-logit));
        conf[p] = interior ? fminf(fmaxf(1.f - unc, 0.f), 1.f) : 1.f;
    }
}

// ---------------- launch ------------------------------------------------------
extern "C" void kernel_launch(void* const* d_in, const int* in_sizes, int n_in,
                              void* d_out, int out_size)
{
    const float* latents = (const float*)d_in[0];
    const int*   idx     = (const int*)d_in[1];
    const float* w_in    = (const float*)d_in[2];
    const float* b_in    = (const float*)d_in[3];
    const float* w1s     = (const float*)d_in[4];
    const float* b1s     = (const float*)d_in[5];
    const float* w2s     = (const float*)d_in[6];
    const float* b2s     = (const float*)d_in[7];
    const float* w_out   = (const float*)d_in[8];
    const float* b_out   = (const float*)d_in[9];
    float* out = (float*)d_out;

    float *resin, *h, *tmp, *coutb, *al, *ar;
    cudaGetSymbolAddress((void**)&resin, g_resin);
    cudaGetSymbolAddress((void**)&h,     g_h);
    cudaGetSymbolAddress((void**)&tmp,   g_tmp);
    cudaGetSymbolAddress((void**)&coutb, g_cout);
    cudaGetSymbolAddress((void**)&al,    g_alpha);
    cudaGetSymbolAddress((void**)&ar,    g_araw);

    prep_kernel<<<NIMG, 256>>>(latents, idx, resin, al, ar);

    // conv_in: 25 -> 64, SiLU
    conv3x3_kernel<25, 64, 16, true, false><<<dim3(NIMG, 4), 256>>>(
        resin, w_in, b_in, h, nullptr);

    // residual blocks
    for (int blk = 0; blk < 2; blk++) {
        const float* w1 = w1s + blk * HID * HID * 9;
        const float* b1 = b1s + blk * HID;
        const float* w2 = w2s + blk * HID * HID * 9;
        const float* b2 = b2s + blk * HID;
        conv3x3_kernel<64, 64, 16, true, false><<<dim3(NIMG, 4), 256>>>(
            h, w1, b1, tmp, nullptr);
        conv3x3_kernel<64, 64, 16, false, true><<<dim3(NIMG, 4), 256>>>(
            tmp, w2, b2, h, h);
    }

    // conv_out: 64 -> 9
    conv3x3_kernel<64, 9, 9, false, false><<<dim3(NIMG, 1), 256>>>(
        h, w_out, b_out, coutb, nullptr);

    finalize_kernel<<<NIMG, 256>>>(resin, coutb, al, ar, out);
}

// round 3
// speedup vs baseline: 2.9801x; 2.9801x over previous
#include <cuda_runtime.h>
#include <cstdint>

#define NIMG 512
#define HW   1024

// ----------------------------------------------------------------------------
// scratch (device globals; no runtime allocation)
// ----------------------------------------------------------------------------
__device__ float g_resin[(size_t)NIMG * HW * 32];  // NHWC, 25 real ch + pad
__device__ float g_h[(size_t)NIMG * HW * 64];      // NHWC64
__device__ float g_tmp[(size_t)NIMG * HW * 64];    // NHWC64
__device__ float g_cout[(size_t)NIMG * HW * 16];   // NHWC, 9 real ch + pad
__device__ float g_alpha[NIMG];
__device__ float g_araw[NIMG];

__device__ __forceinline__ uint32_t f2tf32(float f) {
    uint32_t r;
    asm("cvt.rna.tf32.f32 %0, %1;" : "=r"(r) : "f"(f));
    return r;
}

__device__ __forceinline__ void mma_tf32(float d[4], uint32_t a0, uint32_t a1,
                                         uint32_t a2, uint32_t a3,
                                         uint32_t b0, uint32_t b1) {
    asm volatile(
        "mma.sync.aligned.m16n8k8.row.col.f32.tf32.tf32.f32 "
        "{%0,%1,%2,%3}, {%4,%5,%6,%7}, {%8,%9}, {%0,%1,%2,%3};"
        : "+f"(d[0]), "+f"(d[1]), "+f"(d[2]), "+f"(d[3])
        : "r"(a0), "r"(a1), "r"(a2), "r"(a3), "r"(b0), "r"(b1));
}

// ----------------------------------------------------------------------------
// prep: keyframe lerp -> NHWC32 res_in (ch 0-7 z_base, 8-15 z0, 16-23 z1,
//       24 alpha, 25-31 zero)
// ----------------------------------------------------------------------------
__global__ __launch_bounds__(256)
void prep_kernel(const float* __restrict__ latents, const int* __restrict__ idx,
                 float* __restrict__ resin, float* __restrict__ alpha_arr,
                 float* __restrict__ araw_arr)
{
    const int n = blockIdx.x;
    const int b = n >> 7;
    const int t = n & 127;

    int v[9];
#pragma unroll
    for (int k = 0; k < 9; k++) v[k] = idx[b * 9 + k];
#pragma unroll
    for (int i = 1; i < 9; i++) {
        int key = v[i]; int j = i - 1;
        while (j >= 0 && v[j] > key) { v[j + 1] = v[j]; j--; }
        v[j + 1] = key;
    }
    int cnt = 0;
#pragma unroll
    for (int k = 0; k < 9; k++) cnt += (v[k] <= t);
    int seg = min(max(cnt - 1, 0), 7);
    const int t0 = v[seg], t1 = v[seg + 1];
    const float araw = (float)(t - t0) / (float)max(t1 - t0, 1);
    const float a = fminf(fmaxf(araw, 0.f), 1.f);

    const int tid = threadIdx.x;
    const float* L0 = latents + ((size_t)(b * 128 + t0)) * 8 * HW;
    const float* L1 = latents + ((size_t)(b * 128 + t1)) * 8 * HW;
    float* R = resin + (size_t)n * HW * 32;

#pragma unroll
    for (int j = 0; j < 4; j++) {
        const int p = tid + 256 * j;
        float buf[32];
#pragma unroll
        for (int c = 0; c < 8; c++) {
            const float z0 = L0[c * HW + p];
            const float z1 = L1[c * HW + p];
            buf[c]      = (1.f - a) * z0 + a * z1;
            buf[8 + c]  = z0;
            buf[16 + c] = z1;
        }
        buf[24] = a;
#pragma unroll
        for (int c = 25; c < 32; c++) buf[c] = 0.f;
        float4* dst = (float4*)(R + (size_t)p * 32);
#pragma unroll
        for (int q = 0; q < 8; q++)
            dst[q] = make_float4(buf[q*4], buf[q*4+1], buf[q*4+2], buf[q*4+3]);
    }
    if (tid == 0) { alpha_arr[n] = a; araw_arr[n] = araw; }
}

// ----------------------------------------------------------------------------
// implicit-GEMM 3x3 SAME conv via mma.sync m16n8k8 tf32
// One CTA per image. Input NHWC (CG*32 ch), output NHWC (NT8*8 ch).
//
// SMEM:
//  b_s  : [KCH][NT8][32 lanes][2] tf32 bits (pre-swizzled B fragments)
//  X_s  : [204 pixels][PADX] tf32 bits (6x34 window, pixel stride padded)
// ----------------------------------------------------------------------------
template<int CG, int NT8, bool SILU, bool RESID>
__global__ __launch_bounds__(256, 1)
void conv_mma(const float* __restrict__ in, const float* __restrict__ w,
              const float* __restrict__ bias, float* __restrict__ out,
              const float* __restrict__ resid, int cin_real, int co_real)
{
    constexpr int CIN  = CG * 32;
    constexpr int COUT = NT8 * 8;
    constexpr int KCH  = CG * 36;          // number of k8 chunks = CG*9*32/8
    constexpr int PADX = (CG == 1) ? 36 : 68;

    extern __shared__ uint32_t smem[];
    uint32_t* b_s = smem;                       // KCH*NT8*64 words
    uint32_t* X_s = smem + KCH * NT8 * 64;      // 204*PADX words

    const int tid = threadIdx.x;
    const int wid = tid >> 5;
    const int lane = tid & 31;
    const int n = blockIdx.x;

    // ---- stage weights: zero, then scatter into B-fragment layout ----
    for (int i = tid; i < KCH * NT8 * 64; i += 256) b_s[i] = 0u;
    __syncthreads();
    const int WTOT = co_real * cin_real * 9;
    for (int i = tid; i < WTOT; i += 256) {
        const int tap = i % 9;
        const int ci  = (i / 9) % cin_real;
        const int co  = i / (9 * cin_real);
        const int cg  = ci >> 5;
        const int kin = ci & 31;
        const int kg  = (cg * 9 + tap) * 32 + kin;    // global K index
        const int chunk = kg >> 3;
        const int kk    = kg & 7;
        const int h     = kk >> 2;
        const int bl    = ((co & 7) << 2) | (kk & 3);
        const int nt    = co >> 3;
        b_s[(((chunk * NT8 + nt) * 32 + bl) << 1) + h] = f2tf32(w[i]);
    }

    // bias -> registers (2 channels per nt per thread)
    const int kq = lane & 3;
    float bv[NT8][2];
#pragma unroll
    for (int nt = 0; nt < NT8; nt++) {
        bv[nt][0] = bias[nt * 8 + 2 * kq];
        bv[nt][1] = bias[nt * 8 + 2 * kq + 1];
    }

    // per-thread fragment geometry
    const int p0 = wid * 16 + (lane >> 2);
    const int p1 = p0 + 8;
    const int rb0 = (p0 >> 5) * 34 + (p0 & 31);   // window pixel index base
    const int rb1 = (p1 >> 5) * 34 + (p1 & 31);

    __syncthreads();

    for (int mt = 0; mt < 8; mt++) {
        // ---- stage X window: rows 4mt-1..4mt+4, cols -1..32, CIN ch ----
        for (int i = tid; i < 204 * (CIN / 4); i += 256) {
            const int q   = i % (CIN / 4);
            const int pix = i / (CIN / 4);
            const int rr  = pix / 34;
            const int cc  = pix - rr * 34;
            const int gy  = 4 * mt - 1 + rr;
            const int gx  = cc - 1;
            float4 v = make_float4(0.f, 0.f, 0.f, 0.f);
            if (gy >= 0 && gy < 32 && gx >= 0 && gx < 32)
                v = *(const float4*)(in + ((size_t)n * HW + gy * 32 + gx) * CIN + q * 4);
            uint32_t* d = X_s + pix * PADX + q * 4;
            d[0] = f2tf32(v.x); d[1] = f2tf32(v.y);
            d[2] = f2tf32(v.z); d[3] = f2tf32(v.w);
        }
        __syncthreads();

        float d[NT8][4];
#pragma unroll
        for (int nt = 0; nt < NT8; nt++)
#pragma unroll
            for (int q = 0; q < 4; q++) d[nt][q] = 0.f;

        // ---- K loop: cg groups x 9 taps x 4 k8-chunks ----
#pragma unroll
        for (int cg = 0; cg < CG; cg++) {
            for (int tap = 0; tap < 9; tap++) {
                const int dy = tap / 3, dx = tap % 3;
                const uint32_t* A0 = X_s + (rb0 + dy * 34 + dx) * PADX + cg * 32 + kq;
                const uint32_t* A1 = X_s + (rb1 + dy * 34 + dx) * PADX + cg * 32 + kq;
                const int chunk0 = cg * 36 + tap * 4;
#pragma unroll
                for (int k8 = 0; k8 < 4; k8++) {
                    const uint32_t a0 = A0[k8 * 8];
                    const uint32_t a1 = A1[k8 * 8];
                    const uint32_t a2 = A0[k8 * 8 + 4];
                    const uint32_t a3 = A1[k8 * 8 + 4];
                    const uint32_t* bp =
                        b_s + (((chunk0 + k8) * NT8) * 32 + lane) * 2;
#pragma unroll
                    for (int nt = 0; nt < NT8; nt++) {
                        const uint2 b = *(const uint2*)(bp + nt * 64);
                        mma_tf32(d[nt], a0, a1, a2, a3, b.x, b.y);
                    }
                }
            }
        }

        // ---- epilogue: bias (+SiLU) (+residual), NHWC store ----
        const size_t gp0 = (size_t)n * HW + mt * 128 + p0;
        const size_t gp1 = gp0 + 8;
#pragma unroll
        for (int nt = 0; nt < NT8; nt++) {
            const int c = nt * 8 + 2 * kq;
            float v00 = d[nt][0] + bv[nt][0];
            float v01 = d[nt][1] + bv[nt][1];
            float v10 = d[nt][2] + bv[nt][0];
            float v11 = d[nt][3] + bv[nt][1];
            if (SILU) {
                v00 = v00 / (1.f + __expf(-v00));
                v01 = v01 / (1.f + __expf(-v01));
                v10 = v10 / (1.f + __expf(-v10));
                v11 = v11 / (1.f + __expf(-v11));
            }
            if (RESID) {
                const float2 r0 = *(const float2*)(resid + gp0 * COUT + c);
                const float2 r1 = *(const float2*)(resid + gp1 * COUT + c);
                v00 += r0.x; v01 += r0.y; v10 += r1.x; v11 += r1.y;
            }
            *(float2*)(out + gp0 * COUT + c) = make_float2(v00, v01);
            *(float2*)(out + gp1 * COUT + c) = make_float2(v10, v11);
        }
        __syncthreads();   // X_s reused next mt
    }
}

// ----------------------------------------------------------------------------
// finalize: z_hat (NCHW) + conf
// ----------------------------------------------------------------------------
__global__ __launch_bounds__(256)
void finalize_kernel(const float* __restrict__ resin, const float* __restrict__ co,
                     const float* __restrict__ alpha_arr, const float* __restrict__ araw_arr,
                     float* __restrict__ outp)
{
    const int n = blockIdx.x;
    const int tid = threadIdx.x;
    const float a  = alpha_arr[n];
    const float ar = araw_arr[n];
    const float s  = a * (1.f - a);
    const bool interior = (ar > 0.f) && (ar < 1.f);

#pragma unroll
    for (int j = 0; j < 4; j++) {
        const int p = tid + 256 * j;
        const float* R = resin + ((size_t)n * HW + p) * 32;
        const float* O = co + ((size_t)n * HW + p) * 16;
        float zb[8], res[9];
#pragma unroll
        for (int c = 0; c < 8; c++) zb[c] = R[c];
#pragma unroll
        for (int c = 0; c < 9; c++) res[c] = O[c];
#pragma unroll
        for (int c = 0; c < 8; c++)
            outp[((size_t)n * 8 + c) * HW + p] = zb[c] + s * res[c];
        const float unc = 1.f / (1.f + __expf(-res[8]));
        outp[(size_t)NIMG * 8 * HW + (size_t)n * HW + p] =
            interior ? fminf(fmaxf(1.f - unc, 0.f), 1.f) : 1.f;
    }
}

// ----------------------------------------------------------------------------
// launch
// ----------------------------------------------------------------------------
extern "C" void kernel_launch(void* const* d_in, const int* in_sizes, int n_in,
                              void* d_out, int out_size)
{
    const float* latents = (const float*)d_in[0];
    const int*   idx     = (const int*)d_in[1];
    const float* w_in    = (const float*)d_in[2];
    const float* b_in    = (const float*)d_in[3];
    const float* w1s     = (const float*)d_in[4];
    const float* b1s     = (const float*)d_in[5];
    const float* w2s     = (const float*)d_in[6];
    const float* b2s     = (const float*)d_in[7];
    const float* w_out   = (const float*)d_in[8];
    const float* b_out   = (const float*)d_in[9];
    float* outp = (float*)d_out;

    float *resin, *h, *tmp, *coutb, *al, *ar;
    cudaGetSymbolAddress((void**)&resin, g_resin);
    cudaGetSymbolAddress((void**)&h,     g_h);
    cudaGetSymbolAddress((void**)&tmp,   g_tmp);
    cudaGetSymbolAddress((void**)&coutb, g_cout);
    cudaGetSymbolAddress((void**)&al,    g_alpha);
    cudaGetSymbolAddress((void**)&ar,    g_araw);

    // smem sizes (bytes)
    constexpr int SM_IN  = (36 * 8 * 64 + 204 * 36) * 4;   // 103104
    constexpr int SM_HID = (72 * 8 * 64 + 204 * 68) * 4;   // 202944
    constexpr int SM_OUT = (72 * 2 * 64 + 204 * 68) * 4;   //  92352

    cudaFuncSetAttribute(conv_mma<1, 8, true,  false>,
                         cudaFuncAttributeMaxDynamicSharedMemorySize, SM_IN);
    cudaFuncSetAttribute(conv_mma<2, 8, true,  false>,
                         cudaFuncAttributeMaxDynamicSharedMemorySize, SM_HID);
    cudaFuncSetAttribute(conv_mma<2, 8, false, true>,
                         cudaFuncAttributeMaxDynamicSharedMemorySize, SM_HID);
    cudaFuncSetAttribute(conv_mma<2, 2, false, false>,
                         cudaFuncAttributeMaxDynamicSharedMemorySize, SM_OUT);

    prep_kernel<<<NIMG, 256>>>(latents, idx, resin, al, ar);

    // conv_in: 25(->32) -> 64, SiLU
    conv_mma<1, 8, true, false><<<NIMG, 256, SM_IN>>>(
        resin, w_in, b_in, h, nullptr, 25, 64);

    for (int blk = 0; blk < 2; blk++) {
        const float* w1 = w1s + (size_t)blk * 64 * 64 * 9;
        const float* b1 = b1s + blk * 64;
        const float* w2 = w2s + (size_t)blk * 64 * 64 * 9;
        const float* b2 = b2s + blk * 64;
        conv_mma<2, 8, true, false><<<NIMG, 256, SM_HID>>>(
            h, w1, b1, tmp, nullptr, 64, 64);
        conv_mma<2, 8, false, true><<<NIMG, 256, SM_HID>>>(
            tmp, w2, b2, h, h, 64, 64);
    }

    // conv_out: 64 -> 9(->16)
    conv_mma<2, 2, false, false><<<NIMG, 256, SM_OUT>>>(
        h, w_out, b_out, coutb, nullptr, 64, 9);

    finalize_kernel<<<NIMG, 256>>>(resin, coutb, al, ar, outp);
}

// round 4
// speedup vs baseline: 3.7140x; 1.2463x over previous
#include <cuda_runtime.h>
#include <cstdint>

#define NIMG 512
#define HW   1024

// ----------------------------------------------------------------------------
// scratch (device globals; no runtime allocation)
// ----------------------------------------------------------------------------
__device__ float    g_resin[(size_t)NIMG * HW * 32];  // NHWC, 25 real ch + pad
__device__ float    g_h[(size_t)NIMG * HW * 64];      // NHWC64
__device__ float    g_tmp[(size_t)NIMG * HW * 64];    // NHWC64
__device__ float    g_cout[(size_t)NIMG * HW * 16];   // NHWC, 9 real ch + pad
__device__ float    g_alpha[NIMG];
__device__ float    g_araw[NIMG];
__device__ uint32_t g_wfrag[18432 + 4 * 36864 + 9216]; // pre-scattered B frags

// wfrag layout offsets (words)
#define WOFF_IN   0
#define WOFF_HID0 18432
#define WOFF_OUT  (18432 + 4 * 36864)

__device__ __forceinline__ void mma_tf32(float d[4], uint32_t a0, uint32_t a1,
                                         uint32_t a2, uint32_t a3,
                                         uint32_t b0, uint32_t b1) {
    asm volatile(
        "mma.sync.aligned.m16n8k8.row.col.f32.tf32.tf32.f32 "
        "{%0,%1,%2,%3}, {%4,%5,%6,%7}, {%8,%9}, {%0,%1,%2,%3};"
        : "+f"(d[0]), "+f"(d[1]), "+f"(d[2]), "+f"(d[3])
        : "r"(a0), "r"(a1), "r"(a2), "r"(a3), "r"(b0), "r"(b1));
}

__device__ __forceinline__ void cp_async16(uint32_t dst, const void* src, uint32_t srcsize) {
    asm volatile("cp.async.ca.shared.global [%0], [%1], 16, %2;"
                 :: "r"(dst), "l"(src), "r"(srcsize) : "memory");
}
__device__ __forceinline__ void cp_commit() {
    asm volatile("cp.async.commit_group;" ::: "memory");
}
__device__ __forceinline__ void cp_wait0() {
    asm volatile("cp.async.wait_group 0;" ::: "memory");
}
__device__ __forceinline__ uint32_t smem_u32(const void* p) {
    uint32_t a;
    asm("{ .reg .u64 t; cvta.to.shared.u64 t, %1; cvt.u32.u64 %0, t; }"
        : "=r"(a) : "l"(p));
    return a;
}
__device__ __forceinline__ uint32_t f2tf32(float f) {
    uint32_t r;
    asm("cvt.rna.tf32.f32 %0, %1;" : "=r"(r) : "f"(f));
    return r;
}

// ----------------------------------------------------------------------------
// weight prep: natural OIHW -> B-fragment layout (one-time, 6 blocks)
// k-permutation: within each 8-channel group, channel 2q -> k'=q, 2q+1 -> k'=q+4
// so that A-side pairs (k', k'+4) are channel-adjacent (one LDS.64).
// ----------------------------------------------------------------------------
__global__ __launch_bounds__(256)
void wprep_kernel(const float* __restrict__ w_in, const float* __restrict__ w1s,
                  const float* __restrict__ w2s, const float* __restrict__ w_out,
                  uint32_t* __restrict__ wfrag)
{
    const int layer = blockIdx.x;     // 0=in, 1..4=hidden, 5=out
    const int tid = threadIdx.x;

    const float* w;
    int cin, cout, nt8, woff, nwords;
    if (layer == 0)      { w = w_in;  cin = 25; cout = 64; nt8 = 8; woff = WOFF_IN;  nwords = 18432; }
    else if (layer <= 4) {
        const int blk = (layer - 1) >> 1;
        w = ((layer - 1) & 1) ? (w2s + (size_t)blk * 64 * 64 * 9)
                              : (w1s + (size_t)blk * 64 * 64 * 9);
        cin = 64; cout = 64; nt8 = 8; woff = WOFF_HID0 + (layer - 1) * 36864; nwords = 36864;
    }
    else                 { w = w_out; cin = 64; cout = 9;  nt8 = 2; woff = WOFF_OUT; nwords = 9216; }

    for (int i = tid; i < nwords; i += 256) wfrag[woff + i] = 0u;
    __syncthreads();

    const int wtot = cout * cin * 9;
    for (int i = tid; i < wtot; i += 256) {
        const int tap = i % 9;
        const int ci  = (i / 9) % cin;
        const int co  = i / (9 * cin);
        const int cg  = ci >> 5;
        const int kin = ci & 31;
        // permuted k within 32-group
        const int w8  = kin & 7;
        const int kkp = (kin & 24) | (w8 >> 1) | ((w8 & 1) << 2);
        const int kg  = (cg * 9 + tap) * 32 + kkp;
        const int chunk = kg >> 3;
        const int kk    = kg & 7;
        const int h     = kk >> 2;
        const int bl    = ((co & 7) << 2) | (kk & 3);
        const int nt    = co >> 3;
        wfrag[woff + (((chunk * nt8 + nt) * 32 + bl) << 1) + h] = f2tf32(w[i]);
    }
}

// ----------------------------------------------------------------------------
// prep: keyframe lerp -> NHWC32 res_in
// ----------------------------------------------------------------------------
__global__ __launch_bounds__(256)
void prep_kernel(const float* __restrict__ latents, const int* __restrict__ idx,
                 float* __restrict__ resin, float* __restrict__ alpha_arr,
                 float* __restrict__ araw_arr)
{
    const int n = blockIdx.x;
    const int b = n >> 7;
    const int t = n & 127;

    int v[9];
#pragma unroll
    for (int k = 0; k < 9; k++) v[k] = idx[b * 9 + k];
#pragma unroll
    for (int i = 1; i < 9; i++) {
        int key = v[i]; int j = i - 1;
        while (j >= 0 && v[j] > key) { v[j + 1] = v[j]; j--; }
        v[j + 1] = key;
    }
    int cnt = 0;
#pragma unroll
    for (int k = 0; k < 9; k++) cnt += (v[k] <= t);
    int seg = min(max(cnt - 1, 0), 7);
    const int t0 = v[seg], t1 = v[seg + 1];
    const float araw = (float)(t - t0) / (float)max(t1 - t0, 1);
    const float a = fminf(fmaxf(araw, 0.f), 1.f);

    const int tid = threadIdx.x;
    const float* L0 = latents + ((size_t)(b * 128 + t0)) * 8 * HW;
    const float* L1 = latents + ((size_t)(b * 128 + t1)) * 8 * HW;
    float* R = resin + (size_t)n * HW * 32;

#pragma unroll
    for (int j = 0; j < 4; j++) {
        const int p = tid + 256 * j;
        float buf[32];
#pragma unroll
        for (int c = 0; c < 8; c++) {
            const float z0 = L0[c * HW + p];
            const float z1 = L1[c * HW + p];
            buf[c]      = (1.f - a) * z0 + a * z1;
            buf[8 + c]  = z0;
            buf[16 + c] = z1;
        }
        buf[24] = a;
#pragma unroll
        for (int c = 25; c < 32; c++) buf[c] = 0.f;
        float4* dst = (float4*)(R + (size_t)p * 32);
#pragma unroll
        for (int q = 0; q < 8; q++)
            dst[q] = make_float4(buf[q*4], buf[q*4+1], buf[q*4+2], buf[q*4+3]);
    }
    if (tid == 0) { alpha_arr[n] = a; araw_arr[n] = araw; }
}

// ----------------------------------------------------------------------------
// implicit-GEMM 3x3 SAME conv via mma.sync m16n8k8 tf32 (truncated fp32 feed)
// One CTA per image. Input NHWC (CG*32 ch), output NHWC (NT8*8 ch).
// ----------------------------------------------------------------------------
template<int CG, int NT8, bool SILU, bool RESID>
__global__ __launch_bounds__(256, 1)
void conv_mma(const float* __restrict__ in, const uint32_t* __restrict__ wfrag,
              const float* __restrict__ bias, float* __restrict__ out,
              const float* __restrict__ resid)
{
    constexpr int CIN  = CG * 32;
    constexpr int COUT = NT8 * 8;
    constexpr int KCH  = CG * 36;          // k8 chunks
    constexpr int PADX = CIN + 8;          // bank-conflict-free pixel stride
    constexpr int BW   = KCH * NT8 * 64;   // B words

    extern __shared__ uint32_t smem[];
    uint32_t* b_s = smem;                  // BW words
    uint32_t* X_s = smem + BW;             // 204*PADX words

    const int tid  = threadIdx.x;
    const int wid  = tid >> 5;
    const int lane = tid & 31;
    const int n    = blockIdx.x;
    const int kq   = lane & 3;

    const uint32_t bs_u = smem_u32(b_s);
    const uint32_t xs_u = smem_u32(X_s);

    // ---- stage B fragments via cp.async (completed together with first X) ----
    for (int i = tid; i < BW / 4; i += 256)
        cp_async16(bs_u + i * 16, wfrag + i * 4, 16);

    // bias -> registers
    float bv[NT8][2];
#pragma unroll
    for (int nt = 0; nt < NT8; nt++) {
        bv[nt][0] = bias[nt * 8 + 2 * kq];
        bv[nt][1] = bias[nt * 8 + 2 * kq + 1];
    }

    // fragment geometry
    const int p0  = wid * 16 + (lane >> 2);
    const int p1  = p0 + 8;
    const int rb0 = (p0 >> 5) * 34 + (p0 & 31);
    const int rb1 = (p1 >> 5) * 34 + (p1 & 31);

    constexpr int CHK = CIN / 4;           // float4 chunks per pixel

    for (int mt = 0; mt < 8; mt++) {
        // ---- stage X window: rows 4mt-1..4mt+4, cols -1..32 ----
        for (int i = tid; i < 204 * CHK; i += 256) {
            const int q   = i % CHK;
            const int pix = i / CHK;
            const int rr  = pix / 34;
            const int cc  = pix - rr * 34;
            const int gy  = 4 * mt - 1 + rr;
            const int gx  = cc - 1;
            const bool ok = (gy >= 0) && (gy < 32) && (gx >= 0) && (gx < 32);
            const float* src = in + ((size_t)n * HW + (ok ? gy * 32 + gx : 0)) * CIN + q * 4;
            cp_async16(xs_u + (pix * PADX + q * 4) * 4, src, ok ? 16u : 0u);
        }
        cp_commit();
        cp_wait0();
        __syncthreads();

        float d[NT8][4];
#pragma unroll
        for (int nt = 0; nt < NT8; nt++)
#pragma unroll
            for (int q = 0; q < 4; q++) d[nt][q] = 0.f;

#pragma unroll
        for (int cg = 0; cg < CG; cg++) {
#pragma unroll
            for (int tap = 0; tap < 9; tap++) {
                const int toff = (tap / 3) * 34 + (tap % 3);
                const uint32_t* A0 = X_s + (rb0 + toff) * PADX + cg * 32 + 2 * kq;
                const uint32_t* A1 = X_s + (rb1 + toff) * PADX + cg * 32 + 2 * kq;
                const int chunk0 = (cg * 9 + tap) * 4;
#pragma unroll
                for (int k8 = 0; k8 < 4; k8++) {
                    const uint2 pa = *(const uint2*)(A0 + k8 * 8);
                    const uint2 pb = *(const uint2*)(A1 + k8 * 8);
                    const uint32_t* bp = b_s + (((chunk0 + k8) * NT8) * 32 + lane) * 2;
#pragma unroll
                    for (int nt = 0; nt < NT8; nt++) {
                        const uint2 b = *(const uint2*)(bp + nt * 64);
                        mma_tf32(d[nt], pa.x, pb.x, pa.y, pb.y, b.x, b.y);
                    }
                }
            }
        }

        // ---- epilogue ----
        const size_t gp0 = (size_t)n * HW + mt * 128 + p0;
        const size_t gp1 = gp0 + 8;
#pragma unroll
        for (int nt = 0; nt < NT8; nt++) {
            const int c = nt * 8 + 2 * kq;
            float v00 = d[nt][0] + bv[nt][0];
            float v01 = d[nt][1] + bv[nt][1];
            float v10 = d[nt][2] + bv[nt][0];
            float v11 = d[nt][3] + bv[nt][1];
            if (SILU) {
                v00 = v00 / (1.f + __expf(-v00));
                v01 = v01 / (1.f + __expf(-v01));
                v10 = v10 / (1.f + __expf(-v10));
                v11 = v11 / (1.f + __expf(-v11));
            }
            if (RESID) {
                const float2 r0 = *(const float2*)(resid + gp0 * COUT + c);
                const float2 r1 = *(const float2*)(resid + gp1 * COUT + c);
                v00 += r0.x; v01 += r0.y; v10 += r1.x; v11 += r1.y;
            }
            *(float2*)(out + gp0 * COUT + c) = make_float2(v00, v01);
            *(float2*)(out + gp1 * COUT + c) = make_float2(v10, v11);
        }
        __syncthreads();   // X_s reused next mt
    }
}

// ----------------------------------------------------------------------------
// finalize: z_hat (NCHW) + conf
// ----------------------------------------------------------------------------
__global__ __launch_bounds__(256)
void finalize_kernel(const float* __restrict__ resin, const float* __restrict__ co,
                     const float* __restrict__ alpha_arr, const float* __restrict__ araw_arr,
                     float* __restrict__ outp)
{
    const int n = blockIdx.x;
    const int tid = threadIdx.x;
    const float a  = alpha_arr[n];
    const float ar = araw_arr[n];
    const float s  = a * (1.f - a);
    const bool interior = (ar > 0.f) && (ar < 1.f);

#pragma unroll
    for (int j = 0; j < 4; j++) {
        const int p = tid + 256 * j;
        const float* R = resin + ((size_t)n * HW + p) * 32;
        const float* O = co + ((size_t)n * HW + p) * 16;
        float zb[8], res[9];
#pragma unroll
        for (int c = 0; c < 8; c++) zb[c] = R[c];
#pragma unroll
        for (int c = 0; c < 9; c++) res[c] = O[c];
#pragma unroll
        for (int c = 0; c < 8; c++)
            outp[((size_t)n * 8 + c) * HW + p] = zb[c] + s * res[c];
        const float unc = 1.f / (1.f + __expf(-res[8]));
        outp[(size_t)NIMG * 8 * HW + (size_t)n * HW + p] =
            interior ? fminf(fmaxf(1.f - unc, 0.f), 1.f) : 1.f;
    }
}

// ----------------------------------------------------------------------------
// launch
// ----------------------------------------------------------------------------
extern "C" void kernel_launch(void* const* d_in, const int* in_sizes, int n_in,
                              void* d_out, int out_size)
{
    const float* latents = (const float*)d_in[0];
    const int*   idx     = (const int*)d_in[1];
    const float* w_in    = (const float*)d_in[2];
    const float* b_in    = (const float*)d_in[3];
    const float* w1s     = (const float*)d_in[4];
    const float* b1s     = (const float*)d_in[5];
    const float* w2s     = (const float*)d_in[6];
    const float* b2s     = (const float*)d_in[7];
    const float* w_out   = (const float*)d_in[8];
    const float* b_out   = (const float*)d_in[9];
    float* outp = (float*)d_out;

    float *resin, *h, *tmp, *coutb, *al, *ar;
    uint32_t* wfrag;
    cudaGetSymbolAddress((void**)&resin, g_resin);
    cudaGetSymbolAddress((void**)&h,     g_h);
    cudaGetSymbolAddress((void**)&tmp,   g_tmp);
    cudaGetSymbolAddress((void**)&coutb, g_cout);
    cudaGetSymbolAddress((void**)&al,    g_alpha);
    cudaGetSymbolAddress((void**)&ar,    g_araw);
    cudaGetSymbolAddress((void**)&wfrag, g_wfrag);

    // smem bytes: B + X
    constexpr int SM_IN  = (36 * 8 * 64 + 204 * 40) * 4;   // 106368
    constexpr int SM_HID = (72 * 8 * 64 + 204 * 72) * 4;   // 206208
    constexpr int SM_OUT = (72 * 2 * 64 + 204 * 72) * 4;   //  95616

    cudaFuncSetAttribute(conv_mma<1, 8, true,  false>,
                         cudaFuncAttributeMaxDynamicSharedMemorySize, SM_IN);
    cudaFuncSetAttribute(conv_mma<2, 8, true,  false>,
                         cudaFuncAttributeMaxDynamicSharedMemorySize, SM_HID);
    cudaFuncSetAttribute(conv_mma<2, 8, false, true>,
                         cudaFuncAttributeMaxDynamicSharedMemorySize, SM_HID);
    cudaFuncSetAttribute(conv_mma<2, 2, false, false>,
                         cudaFuncAttributeMaxDynamicSharedMemorySize, SM_OUT);

    wprep_kernel<<<6, 256>>>(w_in, w1s, w2s, w_out, wfrag);
    prep_kernel<<<NIMG, 256>>>(latents, idx, resin, al, ar);

    // conv_in: 25(->32) -> 64, SiLU
    conv_mma<1, 8, true, false><<<NIMG, 256, SM_IN>>>(
        resin, wfrag + WOFF_IN, b_in, h, nullptr);

    for (int blk = 0; blk < 2; blk++) {
        const float* b1 = b1s + blk * 64;
        const float* b2 = b2s + blk * 64;
        conv_mma<2, 8, true, false><<<NIMG, 256, SM_HID>>>(
            h, wfrag + WOFF_HID0 + (2 * blk) * 36864, b1, tmp, nullptr);
        conv_mma<2, 8, false, true><<<NIMG, 256, SM_HID>>>(
            tmp, wfrag + WOFF_HID0 + (2 * blk + 1) * 36864, b2, h, h);
    }

    // conv_out: 64 -> 9(->16)
    conv_mma<2, 2, false, false><<<NIMG, 256, SM_OUT>>>(
        h, wfrag + WOFF_OUT, b_out, coutb, nullptr);

    finalize_kernel<<<NIMG, 256>>>(resin, coutb, al, ar, outp);
}